// round 14
// baseline (speedup 1.0000x reference)
#include <cuda_runtime.h>
#include <cuda_fp16.h>
#include <math.h>
#include <stdint.h>

// ---------------------------------------------------------------------------
// GSDecoder round 14: occupancy-first GEMM. template<MB,NWG>:
//   qkv/mlp1 : <2,4> 64x128 tiles, 3 CTAs/SM (85-reg cap)
//   wo/mlp2  : <1,2> 64x64 tiles, 512 blocks (full waves)
// Numerics unchanged from round 11 (single-pass fp16, rel_err 7.16e-4).
// ---------------------------------------------------------------------------

#define NTOK   4096
#define CDIM   512
#define HEADS  8
#define DHEAD  64
#define LAYERS 8
#define MLPDIM 2048
#define OUTC   56
#define NGAUSS 4

#define ASCALE     256.0f
#define INV_ASCALE 0.00390625f
#define QK_SCALE   1.9073486328125e-6f   // 1/(256*256) / 8

// ------------------------- scratch (device globals) ------------------------
__device__ float g_h  [NTOK * CDIM];

__device__ __half g_ah[NTOK * CDIM];
__device__ __half g_qh[NTOK * 3 * CDIM];
__device__ __half g_oh[NTOK * CDIM];
__device__ __half g_mh[NTOK * MLPDIM];

__device__ __half g_wqkv_h[LAYERS * CDIM * 3 * CDIM];
__device__ __half g_wo_h  [LAYERS * CDIM * CDIM];
__device__ __half g_wm1_h [LAYERS * CDIM * MLPDIM];
__device__ __half g_wm2_h [LAYERS * MLPDIM * CDIM];

// ------------------------------ helpers ------------------------------------
__device__ __forceinline__ float gelu_f(float x) {
    float x3 = x * x * x;
    return 0.5f * x * (1.0f + tanhf(0.7978845608028654f * (x + 0.044715f * x3)));
}

__device__ __forceinline__ void ldsm_x4(unsigned* r, unsigned addr) {
    asm volatile("ldmatrix.sync.aligned.m8n8.x4.shared.b16 {%0,%1,%2,%3}, [%4];"
                 : "=r"(r[0]), "=r"(r[1]), "=r"(r[2]), "=r"(r[3]) : "r"(addr));
}
__device__ __forceinline__ void ldsm_x4t(unsigned* r, unsigned addr) {
    asm volatile("ldmatrix.sync.aligned.m8n8.x4.trans.shared.b16 {%0,%1,%2,%3}, [%4];"
                 : "=r"(r[0]), "=r"(r[1]), "=r"(r[2]), "=r"(r[3]) : "r"(addr));
}
__device__ __forceinline__ void ldsm_x2t(unsigned* r, unsigned addr) {
    asm volatile("ldmatrix.sync.aligned.m8n8.x2.trans.shared.b16 {%0,%1}, [%2];"
                 : "=r"(r[0]), "=r"(r[1]) : "r"(addr));
}
__device__ __forceinline__ void mma16816h(float* c, const unsigned* a, const unsigned* b) {
    asm volatile("mma.sync.aligned.m16n8k16.row.col.f32.f16.f16.f32 "
                 "{%0,%1,%2,%3}, {%4,%5,%6,%7}, {%8,%9}, {%0,%1,%2,%3};"
                 : "+f"(c[0]), "+f"(c[1]), "+f"(c[2]), "+f"(c[3])
                 : "r"(a[0]), "r"(a[1]), "r"(a[2]), "r"(a[3]),
                   "r"(b[0]), "r"(b[1]));
}
__device__ __forceinline__ void cpa16(unsigned dst, const void* src) {
    asm volatile("cp.async.cg.shared.global [%0], [%1], 16;" :: "r"(dst), "l"(src));
}
__device__ __forceinline__ void cpa_commit() { asm volatile("cp.async.commit_group;"); }
template <int NWAIT>
__device__ __forceinline__ void cpa_wait() {
    asm volatile("cp.async.wait_group %0;" :: "n"(NWAIT));
}

__device__ __forceinline__ unsigned pack_h2(float x, float y) {
    __half2 H = __halves2half2(__float2half_rn(x * ASCALE), __float2half_rn(y * ASCALE));
    return *(unsigned*)&H;
}

// ----------------------- merged weight fp16 cast ---------------------------
__global__ void wcast_all_kernel(const float* __restrict__ s0, __half* __restrict__ d0, int n0,
                                 const float* __restrict__ s1, __half* __restrict__ d1, int n1,
                                 const float* __restrict__ s2, __half* __restrict__ d2, int n2,
                                 const float* __restrict__ s3, __half* __restrict__ d3, int n3)
{
    int i = blockIdx.x * 256 + threadIdx.x;
    const float* src; __half* dst;
    if (i < n0)                 { src = s0; dst = d0; }
    else if ((i -= n0) < n1)    { src = s1; dst = d1; }
    else if ((i -= n1) < n2)    { src = s2; dst = d2; }
    else if ((i -= n2) < n3)    { src = s3; dst = d3; }
    else return;
    float4 v = ((const float4*)src)[i];
    __half2 a = __halves2half2(__float2half_rn(v.x), __float2half_rn(v.y));
    __half2 b = __halves2half2(__float2half_rn(v.z), __float2half_rn(v.w));
    ((__half2*)dst)[i * 2]     = a;
    ((__half2*)dst)[i * 2 + 1] = b;
}

// ------------------------------ embed + PE ---------------------------------
__global__ void embed_kernel(const float* __restrict__ feats,
                             const int*   __restrict__ coords,
                             const float* __restrict__ ex,
                             const float* __restrict__ ey,
                             const float* __restrict__ ez,
                             const float* __restrict__ w_in,
                             const float* __restrict__ b_in)
{
    int n = blockIdx.x;
    int c = threadIdx.x;
    const float* f = feats + (size_t)n * 8;
    float acc = b_in[c];
#pragma unroll
    for (int l = 0; l < 8; l++) acc += f[l] * w_in[l * CDIM + c];

    int cx = coords[n * 4 + 1];
    int cy = coords[n * 4 + 2];
    int cz = coords[n * 4 + 3];
    float pe;
    if (c < 170)      pe = ex[cx * 170 + c];
    else if (c < 340) pe = ey[cy * 170 + (c - 170)];
    else              pe = ez[cz * 172 + (c - 340)];
    g_h[(size_t)n * CDIM + c] = acc + pe;
}

// ----------------------- warp-per-row layernorm ----------------------------
__global__ void __launch_bounds__(256)
ln_kernel(const float* __restrict__ x,
          const float* __restrict__ g,
          const float* __restrict__ b,
          __half* __restrict__ oh,
          float eps)
{
    int warp = threadIdx.x >> 5;
    int lane = threadIdx.x & 31;
    int n = blockIdx.x * 8 + warp;
    const float4* xr = (const float4*)(x + (size_t)n * CDIM);

    float4 v[4];
    float s = 0.f, s2 = 0.f;
#pragma unroll
    for (int k = 0; k < 4; k++) {
        v[k] = xr[lane + k * 32];
        s  += v[k].x + v[k].y + v[k].z + v[k].w;
        s2 += v[k].x * v[k].x + v[k].y * v[k].y
            + v[k].z * v[k].z + v[k].w * v[k].w;
    }
#pragma unroll
    for (int off = 16; off; off >>= 1) {
        s  += __shfl_xor_sync(0xffffffffu, s,  off);
        s2 += __shfl_xor_sync(0xffffffffu, s2, off);
    }
    float mean = s * (1.0f / 512.0f);
    float var  = s2 * (1.0f / 512.0f) - mean * mean;
    if (var < 0.f) var = 0.f;
    float r = rsqrtf(var + eps);

#pragma unroll
    for (int k = 0; k < 4; k++) {
        int c = (lane + k * 32) * 4;
        float4 gv = *(const float4*)(g + c);
        float4 bv = *(const float4*)(b + c);
        float o0 = (v[k].x - mean) * r * gv.x + bv.x;
        float o1 = (v[k].y - mean) * r * gv.y + bv.y;
        float o2 = (v[k].z - mean) * r * gv.z + bv.z;
        float o3 = (v[k].w - mean) * r * gv.w + bv.w;
        uint2 pk;
        pk.x = pack_h2(o0, o1);
        pk.y = pack_h2(o2, o3);
        *(uint2*)(oh + (size_t)n * CDIM + c) = pk;
    }
}

// ------ single-pass fp16 GEMM, 3-stage pipeline, templated tile shape ------
// MB = 16-row m-blocks per warp, NWG = warp columns (32 cols each).
// tile = (8/NWG * 16 * MB) x (32 * NWG)
#define BK2 32
#define ASTR2 40

template<int MB, int NWG>
__global__ void __launch_bounds__(256, 3)
gemm_f16_kernel(const __half* __restrict__ Ah,
                const __half* __restrict__ Bh,
                const float* __restrict__ bias, float* __restrict__ Cf,
                __half* __restrict__ Ch,
                int M, int N, int K, int epi)
{
    constexpr int MG   = 8 / NWG;
    constexpr int BMT  = MG * 16 * MB;
    constexpr int BNT  = 32 * NWG;
    constexpr int BSTR = BNT + 8;
    constexpr int A_PL = BMT * ASTR2;
    constexpr int B_PL = 32 * BSTR;
    constexpr int STG3 = A_PL + B_PL;

    extern __shared__ __align__(16) __half smemh[];

    const int tid  = threadIdx.x;
    const int wid  = tid >> 5;
    const int lane = tid & 31;
    const int n0 = blockIdx.x * BNT;
    const int m0 = blockIdx.y * BMT;
    const int wm = (wid / NWG) * (16 * MB);
    const int wn = (wid % NWG) * 32;

    float acc[MB][4][4];
#pragma unroll
    for (int i = 0; i < MB; i++)
#pragma unroll
        for (int j = 0; j < 4; j++)
#pragma unroll
            for (int k = 0; k < 4; k++) acc[i][j][k] = 0.f;

    const int a_row = tid >> 2,  a_off = (tid & 3) << 3;

    auto stage = [&](int s, int k0) {
        __half* base = smemh + s * STG3;
#pragma unroll
        for (int r = 0; r < BMT; r += 64)
            cpa16((unsigned)__cvta_generic_to_shared(base + (a_row + r) * ASTR2 + a_off),
                  Ah + (size_t)(m0 + a_row + r) * K + k0 + a_off);
        __half* d = base + A_PL;
        if (NWG == 4) {
            int b_row = tid >> 3, b_c = (tid & 7) << 4;
            cpa16((unsigned)__cvta_generic_to_shared(d + b_row * BSTR + b_c),
                  Bh + (size_t)(k0 + b_row) * N + n0 + b_c);
            cpa16((unsigned)__cvta_generic_to_shared(d + b_row * BSTR + b_c + 8),
                  Bh + (size_t)(k0 + b_row) * N + n0 + b_c + 8);
        } else {
            int b_row = tid >> 3, b_c = (tid & 7) << 3;
            cpa16((unsigned)__cvta_generic_to_shared(d + b_row * BSTR + b_c),
                  Bh + (size_t)(k0 + b_row) * N + n0 + b_c);
        }
        cpa_commit();
    };

    const int KT = K / BK2;
    stage(0, 0);
    stage(1, BK2);
    int sbuf = 2;
    for (int kt = 0; kt < KT; kt++) {
        if (kt + 1 < KT) cpa_wait<1>();
        else             cpa_wait<0>();
        __syncthreads();

        int buf = kt % 3;
        if (kt + 2 < KT) {
            stage(sbuf, (kt + 2) * BK2);
            sbuf = (sbuf + 1) % 3;
        }

        __half* base = smemh + buf * STG3;
        unsigned aH = (unsigned)__cvta_generic_to_shared(
            base + (wm + (lane & 15)) * ASTR2 + ((lane >> 4) << 3));
        unsigned bH = (unsigned)__cvta_generic_to_shared(
            base + A_PL + (lane & 15) * BSTR + wn);

#pragma unroll
        for (int ks = 0; ks < 2; ks++) {
            unsigned bh[4][2];
#pragma unroll
            for (int nb = 0; nb < 4; nb++) {
                unsigned off = (unsigned)(ks * 16 * BSTR) * 2 + nb * 16;
                ldsm_x2t(bh[nb], bH + off);
            }
#pragma unroll
            for (int mb = 0; mb < MB; mb++) {
                unsigned ah[4];
                unsigned off = (unsigned)(mb * 16 * ASTR2 + ks * 16) * 2;
                ldsm_x4(ah, aH + off);
#pragma unroll
                for (int nb = 0; nb < 4; nb++)
                    mma16816h(acc[mb][nb], ah, bh[nb]);
            }
        }
        __syncthreads();
    }

#pragma unroll
    for (int mb = 0; mb < MB; mb++) {
        int m = m0 + wm + mb * 16 + (lane >> 2);
#pragma unroll
        for (int nb = 0; nb < 4; nb++) {
            int n = n0 + wn + nb * 8 + ((lane & 3) << 1);
            float2 bv = *(const float2*)(bias + n);
            float c0 = acc[mb][nb][0] * INV_ASCALE + bv.x;
            float c1 = acc[mb][nb][1] * INV_ASCALE + bv.y;
            float c2 = acc[mb][nb][2] * INV_ASCALE + bv.x;
            float c3 = acc[mb][nb][3] * INV_ASCALE + bv.y;
            if (epi >= 2) {
                if (epi == 2) {
                    c0 = gelu_f(c0); c1 = gelu_f(c1);
                    c2 = gelu_f(c2); c3 = gelu_f(c3);
                }
                *(unsigned*)(Ch + (size_t)m * N + n)       = pack_h2(c0, c1);
                *(unsigned*)(Ch + (size_t)(m + 8) * N + n) = pack_h2(c2, c3);
            } else {
                float* p0 = Cf + (size_t)m * N + n;
                float* p1 = Cf + (size_t)(m + 8) * N + n;
                if (epi == 1) {
                    float2 r0 = *(float2*)p0;
                    float2 r1 = *(float2*)p1;
                    c0 += r0.x; c1 += r0.y; c2 += r1.x; c3 += r1.y;
                }
                *(float2*)p0 = make_float2(c0, c1);
                *(float2*)p1 = make_float2(c2, c3);
            }
        }
    }
}

#define GSMEM_24 (3 * (64 * ASTR2 + 32 * 136) * 2)   // <2,4>: 41472 B
#define GSMEM_12 (3 * (64 * ASTR2 + 32 * 72) * 2)    // <1,2>: 29184 B

// ---- flash attention: single-pass fp16, double-buffered K/V staging -------
#define ASTR 88
#define TILE_H (64 * ASTR)
#define AQH  0
#define AKV0 TILE_H
#define ATT_SMEM (5 * TILE_H * 2)

__global__ void __launch_bounds__(128)
attn_mma_kernel(const __half* __restrict__ qkvh,
                __half* __restrict__ oh)
{
    extern __shared__ __align__(16) __half sm[];
    const int tid  = threadIdx.x;
    const int wid  = tid >> 5;
    const int lane = tid & 31;
    const int qt = blockIdx.x, h = blockIdx.y, w = blockIdx.z;
    const int tok0 = w * 512;
    const int q0   = qt * 64;
    const int qoff = h * DHEAD;
    const int koff = CDIM + h * DHEAD;
    const int voff = 2 * CDIM + h * DHEAD;
    const int wm   = wid * 16;

    const unsigned sQH = (unsigned)__cvta_generic_to_shared(&sm[AQH]);
    const unsigned sKV = (unsigned)__cvta_generic_to_shared(&sm[AKV0]);

#pragma unroll
    for (int i = 0; i < 4; i++) {
        int id = tid + i * 128;
        int r = id >> 3, c = (id & 7) << 3;
        cpa16(sQH + (unsigned)(r * ASTR + c) * 2,
              qkvh + (size_t)(tok0 + q0 + r) * (3 * CDIM) + qoff + c);
    }
    cpa_commit();

    const int st_r = tid >> 3, st_c = (tid & 7) << 3;
    auto stageKV = [&](int buf, int kt) {
        unsigned base = sKV + (unsigned)(buf * 2 * TILE_H) * 2;
#pragma unroll
        for (int i = 0; i < 4; i++) {
            int r = st_r + i * 16;
            size_t rowb = (size_t)(tok0 + kt * 64 + r) * (3 * CDIM);
            unsigned doff = (unsigned)(r * ASTR + st_c) * 2;
            cpa16(base + doff, qkvh + rowb + koff + st_c);
            cpa16(base + (unsigned)TILE_H * 2 + doff, qkvh + rowb + voff + st_c);
        }
        cpa_commit();
    };

    stageKV(0, 0);
    cpa_wait<1>();
    __syncthreads();

    unsigned qh[4][4];
    {
        int row = wm + (lane & 15);
        int coloff = (lane >> 4) << 3;
#pragma unroll
        for (int ks = 0; ks < 4; ks++)
            ldsm_x4(qh[ks], sQH + (unsigned)(row * ASTR + ks * 16 + coloff) * 2);
    }

    float m0 = -1e30f, m1 = -1e30f, l0 = 0.f, l1 = 0.f;
    float oacc[8][4];
#pragma unroll
    for (int i = 0; i < 8; i++)
#pragma unroll
        for (int j = 0; j < 4; j++) oacc[i][j] = 0.f;

    const int k_key  = ((lane >> 4) << 3) + (lane & 7);
    const int k_kc   = ((lane >> 3) & 1) << 3;
    const int v_kr   = (((lane >> 3) & 1) << 3) + (lane & 7);
    const int v_col  = (lane >> 4) << 3;

    for (int kt = 0; kt < 8; kt++) {
        if (kt + 1 < 8) { stageKV((kt + 1) & 1, kt + 1); cpa_wait<1>(); }
        else            { cpa_wait<0>(); }
        __syncthreads();

        unsigned sKH = sKV + (unsigned)((kt & 1) * 2 * TILE_H) * 2;
        unsigned sVH = sKH + (unsigned)TILE_H * 2;

        float s[8][4];
#pragma unroll
        for (int i = 0; i < 8; i++)
#pragma unroll
            for (int j = 0; j < 4; j++) s[i][j] = 0.f;

#pragma unroll
        for (int p = 0; p < 4; p++) {
#pragma unroll
            for (int ks = 0; ks < 4; ks++) {
                unsigned kb[4];
                unsigned off = (unsigned)((p * 16 + k_key) * ASTR + ks * 16 + k_kc) * 2;
                ldsm_x4(kb, sKH + off);
                mma16816h(s[2 * p],     qh[ks], &kb[0]);
                mma16816h(s[2 * p + 1], qh[ks], &kb[2]);
            }
        }

        float mx0 = -1e30f, mx1 = -1e30f;
#pragma unroll
        for (int nb = 0; nb < 8; nb++) {
            s[nb][0] *= QK_SCALE; s[nb][1] *= QK_SCALE;
            s[nb][2] *= QK_SCALE; s[nb][3] *= QK_SCALE;
            mx0 = fmaxf(mx0, fmaxf(s[nb][0], s[nb][1]));
            mx1 = fmaxf(mx1, fmaxf(s[nb][2], s[nb][3]));
        }
        mx0 = fmaxf(mx0, __shfl_xor_sync(0xffffffffu, mx0, 1));
        mx0 = fmaxf(mx0, __shfl_xor_sync(0xffffffffu, mx0, 2));
        mx1 = fmaxf(mx1, __shfl_xor_sync(0xffffffffu, mx1, 1));
        mx1 = fmaxf(mx1, __shfl_xor_sync(0xffffffffu, mx1, 2));

        float nm0 = fmaxf(m0, mx0);
        float nm1 = fmaxf(m1, mx1);
        float al0 = __expf(m0 - nm0);
        float al1 = __expf(m1 - nm1);
        m0 = nm0; m1 = nm1;

        float sum0 = 0.f, sum1 = 0.f;
#pragma unroll
        for (int nb = 0; nb < 8; nb++) {
            s[nb][0] = __expf(s[nb][0] - nm0);
            s[nb][1] = __expf(s[nb][1] - nm0);
            s[nb][2] = __expf(s[nb][2] - nm1);
            s[nb][3] = __expf(s[nb][3] - nm1);
            sum0 += s[nb][0] + s[nb][1];
            sum1 += s[nb][2] + s[nb][3];
        }
        sum0 += __shfl_xor_sync(0xffffffffu, sum0, 1);
        sum0 += __shfl_xor_sync(0xffffffffu, sum0, 2);
        sum1 += __shfl_xor_sync(0xffffffffu, sum1, 1);
        sum1 += __shfl_xor_sync(0xffffffffu, sum1, 2);
        l0 = l0 * al0 + sum0;
        l1 = l1 * al1 + sum1;

#pragma unroll
        for (int nb = 0; nb < 8; nb++) {
            oacc[nb][0] *= al0; oacc[nb][1] *= al0;
            oacc[nb][2] *= al1; oacc[nb][3] *= al1;
        }

#pragma unroll
        for (int kk = 0; kk < 4; kk++) {
            unsigned pa[4];
            pa[0] = pack_h2(s[2 * kk][0],     s[2 * kk][1]);
            pa[1] = pack_h2(s[2 * kk][2],     s[2 * kk][3]);
            pa[2] = pack_h2(s[2 * kk + 1][0], s[2 * kk + 1][1]);
            pa[3] = pack_h2(s[2 * kk + 1][2], s[2 * kk + 1][3]);
#pragma unroll
            for (int p = 0; p < 4; p++) {
                unsigned vb[4];
                unsigned off = (unsigned)((kk * 16 + v_kr) * ASTR + p * 16 + v_col) * 2;
                ldsm_x4t(vb, sVH + off);
                mma16816h(oacc[2 * p],     pa, &vb[0]);
                mma16816h(oacc[2 * p + 1], pa, &vb[2]);
            }
        }
        __syncthreads();
    }

    float i0 = 1.0f / (65536.0f * l0);
    float i1 = 1.0f / (65536.0f * l1);
    int r0  = tok0 + q0 + wm + (lane >> 2);
    int col = h * DHEAD + ((lane & 3) << 1);
#pragma unroll
    for (int nb = 0; nb < 8; nb++) {
        size_t p0 = (size_t)r0 * CDIM + col + nb * 8;
        size_t p1 = (size_t)(r0 + 8) * CDIM + col + nb * 8;
        *(unsigned*)(oh + p0) = pack_h2(oacc[nb][0] * i0, oacc[nb][1] * i0);
        *(unsigned*)(oh + p1) = pack_h2(oacc[nb][2] * i1, oacc[nb][3] * i1);
    }
}

// ------------- fused tail: final LN + out-head GEMV + postprocess ----------
__global__ void __launch_bounds__(64)
tail_kernel(const float* __restrict__ hbuf,
            const float* __restrict__ w,
            const float* __restrict__ bo,
            const int*   __restrict__ coords,
            const float* __restrict__ perturb,
            float* __restrict__ out)
{
    __shared__ float row[CDIM];
    __shared__ float ws[4];
    __shared__ float res[OUTC];

    int n = blockIdx.x;
    int tid = threadIdx.x;
    int warp = tid >> 5, lane = tid & 31;

    const float4* xr = (const float4*)(hbuf + (size_t)n * CDIM);
    float4 v0 = xr[tid];
    float4 v1 = xr[tid + 64];
    float s  = v0.x + v0.y + v0.z + v0.w + v1.x + v1.y + v1.z + v1.w;
    float s2 = v0.x * v0.x + v0.y * v0.y + v0.z * v0.z + v0.w * v0.w
             + v1.x * v1.x + v1.y * v1.y + v1.z * v1.z + v1.w * v1.w;
#pragma unroll
    for (int off = 16; off; off >>= 1) {
        s  += __shfl_xor_sync(0xffffffffu, s,  off);
        s2 += __shfl_xor_sync(0xffffffffu, s2, off);
    }
    if (lane == 0) { ws[warp] = s; ws[warp + 2] = s2; }
    __syncthreads();
    float ts  = ws[0] + ws[1];
    float ts2 = ws[2] + ws[3];
    float mean = ts * (1.0f / 512.0f);
    float var  = ts2 * (1.0f / 512.0f) - mean * mean;
    if (var < 0.f) var = 0.f;
    float r = rsqrtf(var + 1e-5f);

    *(float4*)(row + tid * 4) =
        make_float4((v0.x - mean) * r, (v0.y - mean) * r,
                    (v0.z - mean) * r, (v0.w - mean) * r);
    *(float4*)(row + 256 + tid * 4) =
        make_float4((v1.x - mean) * r, (v1.y - mean) * r,
                    (v1.z - mean) * r, (v1.w - mean) * r);
    __syncthreads();

    if (tid < OUTC) {
        float acc = bo[tid];
#pragma unroll 8
        for (int k = 0; k < CDIM; k++)
            acc += row[k] * w[k * OUTC + tid];
        res[tid] = acc;
    }
    __syncthreads();

    if (tid < NGAUSS) {
        int g = tid;
        int idx = n * NGAUSS + g;
#pragma unroll
        for (int j = 0; j < 3; j++) {
            float off = tanhf(res[g * 3 + j] + perturb[g * 3 + j]) * 4.8828125e-4f;
            float xb  = ((float)coords[n * 4 + 1 + j] + 0.5f) * 0.0625f;
            out[idx * 3 + j]          = xb + off;
            out[49152 + idx * 3 + j]  = res[12 + g * 3 + j];
            out[98304 + idx * 3 + j]  = res[24 + g * 3 + j];
        }
#pragma unroll
        for (int j = 0; j < 4; j++)
            out[147456 + idx * 4 + j] = res[36 + g * 4 + j];
        out[212992 + idx] = res[52 + g];
    }
}

// ------------------------------- launch ------------------------------------
extern "C" void kernel_launch(void* const* d_in, const int* in_sizes, int n_in,
                              void* d_out, int out_size)
{
    const float* feats   = (const float*)d_in[0];
    const int*   coords  = (const int*)  d_in[1];
    const float* emb_x   = (const float*)d_in[2];
    const float* emb_y   = (const float*)d_in[3];
    const float* emb_z   = (const float*)d_in[4];
    const float* w_in    = (const float*)d_in[5];
    const float* b_in    = (const float*)d_in[6];
    const float* ln1_g   = (const float*)d_in[7];
    const float* ln1_b   = (const float*)d_in[8];
    const float* w_qkv   = (const float*)d_in[9];
    const float* b_qkv   = (const float*)d_in[10];
    const float* w_o     = (const float*)d_in[11];
    const float* b_o     = (const float*)d_in[12];
    const float* ln2_g   = (const float*)d_in[13];
    const float* ln2_b   = (const float*)d_in[14];
    const float* w_m1    = (const float*)d_in[15];
    const float* b_m1    = (const float*)d_in[16];
    const float* w_m2    = (const float*)d_in[17];
    const float* b_m2    = (const float*)d_in[18];
    const float* w_out   = (const float*)d_in[19];
    const float* b_out   = (const float*)d_in[20];
    const float* perturb = (const float*)d_in[21];
    float* out = (float*)d_out;

    float *ph;
    __half *pah, *pqh, *poh, *pmh;
    __half *pwqh, *pwoh, *pw1h, *pw2h;
    cudaGetSymbolAddress((void**)&ph,   g_h);
    cudaGetSymbolAddress((void**)&pah,  g_ah);
    cudaGetSymbolAddress((void**)&pqh,  g_qh);
    cudaGetSymbolAddress((void**)&poh,  g_oh);
    cudaGetSymbolAddress((void**)&pmh,  g_mh);
    cudaGetSymbolAddress((void**)&pwqh, g_wqkv_h);
    cudaGetSymbolAddress((void**)&pwoh, g_wo_h);
    cudaGetSymbolAddress((void**)&pw1h, g_wm1_h);
    cudaGetSymbolAddress((void**)&pw2h, g_wm2_h);

    cudaFuncSetAttribute(attn_mma_kernel,
                         cudaFuncAttributeMaxDynamicSharedMemorySize, ATT_SMEM);
    cudaFuncSetAttribute(gemm_f16_kernel<2, 4>,
                         cudaFuncAttributeMaxDynamicSharedMemorySize, GSMEM_24);
    cudaFuncSetAttribute(gemm_f16_kernel<1, 2>,
                         cudaFuncAttributeMaxDynamicSharedMemorySize, GSMEM_12);

    {
        int n4q = LAYERS * CDIM * 3 * CDIM / 4;
        int n4o = LAYERS * CDIM * CDIM / 4;
        int n4m = LAYERS * CDIM * MLPDIM / 4;
        int tot = n4q + n4o + 2 * n4m;
        wcast_all_kernel<<<(tot + 255) / 256, 256>>>(
            w_qkv, pwqh, n4q, w_o, pwoh, n4o,
            w_m1, pw1h, n4m, w_m2, pw2h, n4m);
    }

    embed_kernel<<<NTOK, CDIM>>>(feats, coords, emb_x, emb_y, emb_z, w_in, b_in);

    for (int l = 0; l < LAYERS; l++) {
        ln_kernel<<<NTOK / 8, 256>>>(ph, ln1_g + l * CDIM, ln1_b + l * CDIM,
                                     pah, 1e-6f);
        gemm_f16_kernel<2, 4><<<dim3(3 * CDIM / 128, NTOK / 64), 256, GSMEM_24>>>(
            pah, pwqh + (size_t)l * CDIM * 3 * CDIM,
            b_qkv + l * 3 * CDIM, nullptr, pqh,
            NTOK, 3 * CDIM, CDIM, 3);
        attn_mma_kernel<<<dim3(8, HEADS, 8), 128, ATT_SMEM>>>(pqh, poh);
        gemm_f16_kernel<1, 2><<<dim3(CDIM / 64, NTOK / 64), 256, GSMEM_12>>>(
            poh, pwoh + (size_t)l * CDIM * CDIM,
            b_o + l * CDIM, ph, nullptr,
            NTOK, CDIM, CDIM, 1);
        ln_kernel<<<NTOK / 8, 256>>>(ph, ln2_g + l * CDIM, ln2_b + l * CDIM,
                                     pah, 1e-6f);
        gemm_f16_kernel<2, 4><<<dim3(MLPDIM / 128, NTOK / 64), 256, GSMEM_24>>>(
            pah, pw1h + (size_t)l * CDIM * MLPDIM,
            b_m1 + l * MLPDIM, nullptr, pmh,
            NTOK, MLPDIM, CDIM, 2);
        gemm_f16_kernel<1, 2><<<dim3(CDIM / 64, NTOK / 64), 256, GSMEM_12>>>(
            pmh, pw2h + (size_t)l * MLPDIM * CDIM,
            b_m2 + l * CDIM, ph, nullptr,
            NTOK, CDIM, MLPDIM, 1);
    }

    tail_kernel<<<NTOK, 64>>>(ph, w_out, b_out, coords, perturb, out);
}

// round 16
// speedup vs baseline: 1.0683x; 1.0683x over previous
#include <cuda_runtime.h>
#include <cuda_fp16.h>
#include <math.h>
#include <stdint.h>

// ---------------------------------------------------------------------------
// GSDecoder round 16 (= round 15 resubmitted after infra failure):
// round-13 shapes (BM128 qkv/mlp1, BM64 wo/mlp2, 3-stage cp.async)
//  + trailing barrier removed from GEMM k-loop (single barrier per k-step;
//    proof: stage(kt) writes buf (kt+2)%3 == (kt-1)%3, and barrier(kt)
//    guarantees all warps finished compute(kt-1) before any stage(kt))
//  + A-fragment software pipelining (ldsm for mb+1 overlaps mb's MMAs)
// Numerics unchanged (single-pass fp16, rel_err 7.16e-4).
// ---------------------------------------------------------------------------

#define NTOK   4096
#define CDIM   512
#define HEADS  8
#define DHEAD  64
#define LAYERS 8
#define MLPDIM 2048
#define OUTC   56
#define NGAUSS 4

#define ASCALE     256.0f
#define INV_ASCALE 0.00390625f
#define QK_SCALE   1.9073486328125e-6f   // 1/(256*256) / 8

// ------------------------- scratch (device globals) ------------------------
__device__ float g_h  [NTOK * CDIM];

__device__ __half g_ah[NTOK * CDIM];
__device__ __half g_qh[NTOK * 3 * CDIM];
__device__ __half g_oh[NTOK * CDIM];
__device__ __half g_mh[NTOK * MLPDIM];

__device__ __half g_wqkv_h[LAYERS * CDIM * 3 * CDIM];
__device__ __half g_wo_h  [LAYERS * CDIM * CDIM];
__device__ __half g_wm1_h [LAYERS * CDIM * MLPDIM];
__device__ __half g_wm2_h [LAYERS * MLPDIM * CDIM];

// ------------------------------ helpers ------------------------------------
__device__ __forceinline__ float gelu_f(float x) {
    float x3 = x * x * x;
    return 0.5f * x * (1.0f + tanhf(0.7978845608028654f * (x + 0.044715f * x3)));
}

__device__ __forceinline__ void ldsm_x4(unsigned* r, unsigned addr) {
    asm volatile("ldmatrix.sync.aligned.m8n8.x4.shared.b16 {%0,%1,%2,%3}, [%4];"
                 : "=r"(r[0]), "=r"(r[1]), "=r"(r[2]), "=r"(r[3]) : "r"(addr));
}
__device__ __forceinline__ void ldsm_x4t(unsigned* r, unsigned addr) {
    asm volatile("ldmatrix.sync.aligned.m8n8.x4.trans.shared.b16 {%0,%1,%2,%3}, [%4];"
                 : "=r"(r[0]), "=r"(r[1]), "=r"(r[2]), "=r"(r[3]) : "r"(addr));
}
__device__ __forceinline__ void ldsm_x2t(unsigned* r, unsigned addr) {
    asm volatile("ldmatrix.sync.aligned.m8n8.x2.trans.shared.b16 {%0,%1}, [%2];"
                 : "=r"(r[0]), "=r"(r[1]) : "r"(addr));
}
__device__ __forceinline__ void mma16816h(float* c, const unsigned* a, const unsigned* b) {
    asm volatile("mma.sync.aligned.m16n8k16.row.col.f32.f16.f16.f32 "
                 "{%0,%1,%2,%3}, {%4,%5,%6,%7}, {%8,%9}, {%0,%1,%2,%3};"
                 : "+f"(c[0]), "+f"(c[1]), "+f"(c[2]), "+f"(c[3])
                 : "r"(a[0]), "r"(a[1]), "r"(a[2]), "r"(a[3]),
                   "r"(b[0]), "r"(b[1]));
}
__device__ __forceinline__ void cpa16(unsigned dst, const void* src) {
    asm volatile("cp.async.cg.shared.global [%0], [%1], 16;" :: "r"(dst), "l"(src));
}
__device__ __forceinline__ void cpa_commit() { asm volatile("cp.async.commit_group;"); }
template <int NWAIT>
__device__ __forceinline__ void cpa_wait() {
    asm volatile("cp.async.wait_group %0;" :: "n"(NWAIT));
}

__device__ __forceinline__ unsigned pack_h2(float x, float y) {
    __half2 H = __halves2half2(__float2half_rn(x * ASCALE), __float2half_rn(y * ASCALE));
    return *(unsigned*)&H;
}

// ----------------------- merged weight fp16 cast ---------------------------
__global__ void wcast_all_kernel(const float* __restrict__ s0, __half* __restrict__ d0, int n0,
                                 const float* __restrict__ s1, __half* __restrict__ d1, int n1,
                                 const float* __restrict__ s2, __half* __restrict__ d2, int n2,
                                 const float* __restrict__ s3, __half* __restrict__ d3, int n3)
{
    int i = blockIdx.x * 256 + threadIdx.x;
    const float* src; __half* dst;
    if (i < n0)                 { src = s0; dst = d0; }
    else if ((i -= n0) < n1)    { src = s1; dst = d1; }
    else if ((i -= n1) < n2)    { src = s2; dst = d2; }
    else if ((i -= n2) < n3)    { src = s3; dst = d3; }
    else return;
    float4 v = ((const float4*)src)[i];
    __half2 a = __halves2half2(__float2half_rn(v.x), __float2half_rn(v.y));
    __half2 b = __halves2half2(__float2half_rn(v.z), __float2half_rn(v.w));
    ((__half2*)dst)[i * 2]     = a;
    ((__half2*)dst)[i * 2 + 1] = b;
}

// ------------------------------ embed + PE ---------------------------------
__global__ void embed_kernel(const float* __restrict__ feats,
                             const int*   __restrict__ coords,
                             const float* __restrict__ ex,
                             const float* __restrict__ ey,
                             const float* __restrict__ ez,
                             const float* __restrict__ w_in,
                             const float* __restrict__ b_in)
{
    int n = blockIdx.x;
    int c = threadIdx.x;
    const float* f = feats + (size_t)n * 8;
    float acc = b_in[c];
#pragma unroll
    for (int l = 0; l < 8; l++) acc += f[l] * w_in[l * CDIM + c];

    int cx = coords[n * 4 + 1];
    int cy = coords[n * 4 + 2];
    int cz = coords[n * 4 + 3];
    float pe;
    if (c < 170)      pe = ex[cx * 170 + c];
    else if (c < 340) pe = ey[cy * 170 + (c - 170)];
    else              pe = ez[cz * 172 + (c - 340)];
    g_h[(size_t)n * CDIM + c] = acc + pe;
}

// ----------------------- warp-per-row layernorm ----------------------------
__global__ void __launch_bounds__(256)
ln_kernel(const float* __restrict__ x,
          const float* __restrict__ g,
          const float* __restrict__ b,
          __half* __restrict__ oh,
          float eps)
{
    int warp = threadIdx.x >> 5;
    int lane = threadIdx.x & 31;
    int n = blockIdx.x * 8 + warp;
    const float4* xr = (const float4*)(x + (size_t)n * CDIM);

    float4 v[4];
    float s = 0.f, s2 = 0.f;
#pragma unroll
    for (int k = 0; k < 4; k++) {
        v[k] = xr[lane + k * 32];
        s  += v[k].x + v[k].y + v[k].z + v[k].w;
        s2 += v[k].x * v[k].x + v[k].y * v[k].y
            + v[k].z * v[k].z + v[k].w * v[k].w;
    }
#pragma unroll
    for (int off = 16; off; off >>= 1) {
        s  += __shfl_xor_sync(0xffffffffu, s,  off);
        s2 += __shfl_xor_sync(0xffffffffu, s2, off);
    }
    float mean = s * (1.0f / 512.0f);
    float var  = s2 * (1.0f / 512.0f) - mean * mean;
    if (var < 0.f) var = 0.f;
    float r = rsqrtf(var + eps);

#pragma unroll
    for (int k = 0; k < 4; k++) {
        int c = (lane + k * 32) * 4;
        float4 gv = *(const float4*)(g + c);
        float4 bv = *(const float4*)(b + c);
        float o0 = (v[k].x - mean) * r * gv.x + bv.x;
        float o1 = (v[k].y - mean) * r * gv.y + bv.y;
        float o2 = (v[k].z - mean) * r * gv.z + bv.z;
        float o3 = (v[k].w - mean) * r * gv.w + bv.w;
        uint2 pk;
        pk.x = pack_h2(o0, o1);
        pk.y = pack_h2(o2, o3);
        *(uint2*)(oh + (size_t)n * CDIM + c) = pk;
    }
}

// ---- single-pass fp16 GEMM, 3-stage, no trailing barrier, A pipelined -----
// MB = 16-row m-blocks per warp (4 -> BM=128, 2 -> BM=64). BN=128, BK=32.
#define BN 128
#define BK2 32
#define ASTR2 40
#define BSTR2 136

template<int MB>
__global__ void __launch_bounds__(256, 2)
gemm_f16_kernel(const __half* __restrict__ Ah,
                const __half* __restrict__ Bh,
                const float* __restrict__ bias, float* __restrict__ Cf,
                __half* __restrict__ Ch,
                int M, int N, int K, int epi)
{
    constexpr int BMT  = 32 * MB;
    constexpr int A_PL = BMT * ASTR2;
    constexpr int B_PL = 32 * BSTR2;
    constexpr int STG3 = A_PL + B_PL;

    extern __shared__ __align__(16) __half smemh[];

    const int tid  = threadIdx.x;
    const int wid  = tid >> 5;
    const int lane = tid & 31;
    const int n0 = blockIdx.x * BN;
    const int m0 = blockIdx.y * BMT;
    const int wm = (wid >> 2) * (16 * MB);
    const int wn = (wid & 3) * 32;

    float acc[MB][4][4];
#pragma unroll
    for (int i = 0; i < MB; i++)
#pragma unroll
        for (int j = 0; j < 4; j++)
#pragma unroll
            for (int k = 0; k < 4; k++) acc[i][j][k] = 0.f;

    const int a_row = tid >> 2,  a_off = (tid & 3) << 3;
    const int b_row = tid >> 3,  b_c = (tid & 7) << 4;

    auto stage = [&](int s, int k0) {
        __half* base = smemh + s * STG3;
        cpa16((unsigned)__cvta_generic_to_shared(base + a_row * ASTR2 + a_off),
              Ah + (size_t)(m0 + a_row) * K + k0 + a_off);
        if (MB == 4)
            cpa16((unsigned)__cvta_generic_to_shared(base + (a_row + 64) * ASTR2 + a_off),
                  Ah + (size_t)(m0 + a_row + 64) * K + k0 + a_off);
        __half* d = base + A_PL;
        cpa16((unsigned)__cvta_generic_to_shared(d + b_row * BSTR2 + b_c),
              Bh + (size_t)(k0 + b_row) * N + n0 + b_c);
        cpa16((unsigned)__cvta_generic_to_shared(d + b_row * BSTR2 + b_c + 8),
              Bh + (size_t)(k0 + b_row) * N + n0 + b_c + 8);
        cpa_commit();
    };

    const int KT = K / BK2;
    stage(0, 0);
    stage(1, BK2);
    int sbuf = 2;
    for (int kt = 0; kt < KT; kt++) {
        if (kt + 1 < KT) cpa_wait<1>();
        else             cpa_wait<0>();
        __syncthreads();              // sole barrier per k-step (see header proof)

        int buf = kt % 3;
        if (kt + 2 < KT) {
            stage(sbuf, (kt + 2) * BK2);
            sbuf = (sbuf + 1) % 3;
        }

        __half* base = smemh + buf * STG3;
        unsigned aH = (unsigned)__cvta_generic_to_shared(
            base + (wm + (lane & 15)) * ASTR2 + ((lane >> 4) << 3));
        unsigned bH = (unsigned)__cvta_generic_to_shared(
            base + A_PL + (lane & 15) * BSTR2 + wn);

#pragma unroll
        for (int ks = 0; ks < 2; ks++) {
            unsigned bh[4][2];
#pragma unroll
            for (int nb = 0; nb < 4; nb++) {
                unsigned off = (unsigned)(ks * 16 * BSTR2) * 2 + nb * 16;
                ldsm_x2t(bh[nb], bH + off);
            }
            // A-frag double buffer: load mb+1 during mb's MMAs
            unsigned ahreg[2][4];
            ldsm_x4(ahreg[0], aH + (unsigned)(ks * 16) * 2);
#pragma unroll
            for (int mb = 0; mb < MB; mb++) {
                if (mb + 1 < MB)
                    ldsm_x4(ahreg[(mb + 1) & 1],
                            aH + (unsigned)((mb + 1) * 16 * ASTR2 + ks * 16) * 2);
#pragma unroll
                for (int nb = 0; nb < 4; nb++)
                    mma16816h(acc[mb][nb], ahreg[mb & 1], bh[nb]);
            }
        }
        // no trailing barrier (next iteration's leading barrier protects reuse)
    }

#pragma unroll
    for (int mb = 0; mb < MB; mb++) {
        int m = m0 + wm + mb * 16 + (lane >> 2);
#pragma unroll
        for (int nb = 0; nb < 4; nb++) {
            int n = n0 + wn + nb * 8 + ((lane & 3) << 1);
            float2 bv = *(const float2*)(bias + n);
            float c0 = acc[mb][nb][0] * INV_ASCALE + bv.x;
            float c1 = acc[mb][nb][1] * INV_ASCALE + bv.y;
            float c2 = acc[mb][nb][2] * INV_ASCALE + bv.x;
            float c3 = acc[mb][nb][3] * INV_ASCALE + bv.y;
            if (epi >= 2) {
                if (epi == 2) {
                    c0 = gelu_f(c0); c1 = gelu_f(c1);
                    c2 = gelu_f(c2); c3 = gelu_f(c3);
                }
                *(unsigned*)(Ch + (size_t)m * N + n)       = pack_h2(c0, c1);
                *(unsigned*)(Ch + (size_t)(m + 8) * N + n) = pack_h2(c2, c3);
            } else {
                float* p0 = Cf + (size_t)m * N + n;
                float* p1 = Cf + (size_t)(m + 8) * N + n;
                if (epi == 1) {
                    float2 r0 = *(float2*)p0;
                    float2 r1 = *(float2*)p1;
                    c0 += r0.x; c1 += r0.y; c2 += r1.x; c3 += r1.y;
                }
                *(float2*)p0 = make_float2(c0, c1);
                *(float2*)p1 = make_float2(c2, c3);
            }
        }
    }
}

#define GSMEM_128 (3 * (128 * ASTR2 + 32 * BSTR2) * 2)
#define GSMEM_64  (3 * (64 * ASTR2 + 32 * BSTR2) * 2)

// ---- flash attention: single-pass fp16, double-buffered K/V staging -------
#define ASTR 88
#define TILE_H (64 * ASTR)
#define AQH  0
#define AKV0 TILE_H
#define ATT_SMEM (5 * TILE_H * 2)

__global__ void __launch_bounds__(128)
attn_mma_kernel(const __half* __restrict__ qkvh,
                __half* __restrict__ oh)
{
    extern __shared__ __align__(16) __half sm[];
    const int tid  = threadIdx.x;
    const int wid  = tid >> 5;
    const int lane = tid & 31;
    const int qt = blockIdx.x, h = blockIdx.y, w = blockIdx.z;
    const int tok0 = w * 512;
    const int q0   = qt * 64;
    const int qoff = h * DHEAD;
    const int koff = CDIM + h * DHEAD;
    const int voff = 2 * CDIM + h * DHEAD;
    const int wm   = wid * 16;

    const unsigned sQH = (unsigned)__cvta_generic_to_shared(&sm[AQH]);
    const unsigned sKV = (unsigned)__cvta_generic_to_shared(&sm[AKV0]);

#pragma unroll
    for (int i = 0; i < 4; i++) {
        int id = tid + i * 128;
        int r = id >> 3, c = (id & 7) << 3;
        cpa16(sQH + (unsigned)(r * ASTR + c) * 2,
              qkvh + (size_t)(tok0 + q0 + r) * (3 * CDIM) + qoff + c);
    }
    cpa_commit();

    const int st_r = tid >> 3, st_c = (tid & 7) << 3;
    auto stageKV = [&](int buf, int kt) {
        unsigned base = sKV + (unsigned)(buf * 2 * TILE_H) * 2;
#pragma unroll
        for (int i = 0; i < 4; i++) {
            int r = st_r + i * 16;
            size_t rowb = (size_t)(tok0 + kt * 64 + r) * (3 * CDIM);
            unsigned doff = (unsigned)(r * ASTR + st_c) * 2;
            cpa16(base + doff, qkvh + rowb + koff + st_c);
            cpa16(base + (unsigned)TILE_H * 2 + doff, qkvh + rowb + voff + st_c);
        }
        cpa_commit();
    };

    stageKV(0, 0);
    cpa_wait<1>();
    __syncthreads();

    unsigned qh[4][4];
    {
        int row = wm + (lane & 15);
        int coloff = (lane >> 4) << 3;
#pragma unroll
        for (int ks = 0; ks < 4; ks++)
            ldsm_x4(qh[ks], sQH + (unsigned)(row * ASTR + ks * 16 + coloff) * 2);
    }

    float m0 = -1e30f, m1 = -1e30f, l0 = 0.f, l1 = 0.f;
    float oacc[8][4];
#pragma unroll
    for (int i = 0; i < 8; i++)
#pragma unroll
        for (int j = 0; j < 4; j++) oacc[i][j] = 0.f;

    const int k_key  = ((lane >> 4) << 3) + (lane & 7);
    const int k_kc   = ((lane >> 3) & 1) << 3;
    const int v_kr   = (((lane >> 3) & 1) << 3) + (lane & 7);
    const int v_col  = (lane >> 4) << 3;

    for (int kt = 0; kt < 8; kt++) {
        if (kt + 1 < 8) { stageKV((kt + 1) & 1, kt + 1); cpa_wait<1>(); }
        else            { cpa_wait<0>(); }
        __syncthreads();

        unsigned sKH = sKV + (unsigned)((kt & 1) * 2 * TILE_H) * 2;
        unsigned sVH = sKH + (unsigned)TILE_H * 2;

        float s[8][4];
#pragma unroll
        for (int i = 0; i < 8; i++)
#pragma unroll
            for (int j = 0; j < 4; j++) s[i][j] = 0.f;

#pragma unroll
        for (int p = 0; p < 4; p++) {
#pragma unroll
            for (int ks = 0; ks < 4; ks++) {
                unsigned kb[4];
                unsigned off = (unsigned)((p * 16 + k_key) * ASTR + ks * 16 + k_kc) * 2;
                ldsm_x4(kb, sKH + off);
                mma16816h(s[2 * p],     qh[ks], &kb[0]);
                mma16816h(s[2 * p + 1], qh[ks], &kb[2]);
            }
        }

        float mx0 = -1e30f, mx1 = -1e30f;
#pragma unroll
        for (int nb = 0; nb < 8; nb++) {
            s[nb][0] *= QK_SCALE; s[nb][1] *= QK_SCALE;
            s[nb][2] *= QK_SCALE; s[nb][3] *= QK_SCALE;
            mx0 = fmaxf(mx0, fmaxf(s[nb][0], s[nb][1]));
            mx1 = fmaxf(mx1, fmaxf(s[nb][2], s[nb][3]));
        }
        mx0 = fmaxf(mx0, __shfl_xor_sync(0xffffffffu, mx0, 1));
        mx0 = fmaxf(mx0, __shfl_xor_sync(0xffffffffu, mx0, 2));
        mx1 = fmaxf(mx1, __shfl_xor_sync(0xffffffffu, mx1, 1));
        mx1 = fmaxf(mx1, __shfl_xor_sync(0xffffffffu, mx1, 2));

        float nm0 = fmaxf(m0, mx0);
        float nm1 = fmaxf(m1, mx1);
        float al0 = __expf(m0 - nm0);
        float al1 = __expf(m1 - nm1);
        m0 = nm0; m1 = nm1;

        float sum0 = 0.f, sum1 = 0.f;
#pragma unroll
        for (int nb = 0; nb < 8; nb++) {
            s[nb][0] = __expf(s[nb][0] - nm0);
            s[nb][1] = __expf(s[nb][1] - nm0);
            s[nb][2] = __expf(s[nb][2] - nm1);
            s[nb][3] = __expf(s[nb][3] - nm1);
            sum0 += s[nb][0] + s[nb][1];
            sum1 += s[nb][2] + s[nb][3];
        }
        sum0 += __shfl_xor_sync(0xffffffffu, sum0, 1);
        sum0 += __shfl_xor_sync(0xffffffffu, sum0, 2);
        sum1 += __shfl_xor_sync(0xffffffffu, sum1, 1);
        sum1 += __shfl_xor_sync(0xffffffffu, sum1, 2);
        l0 = l0 * al0 + sum0;
        l1 = l1 * al1 + sum1;

#pragma unroll
        for (int nb = 0; nb < 8; nb++) {
            oacc[nb][0] *= al0; oacc[nb][1] *= al0;
            oacc[nb][2] *= al1; oacc[nb][3] *= al1;
        }

#pragma unroll
        for (int kk = 0; kk < 4; kk++) {
            unsigned pa[4];
            pa[0] = pack_h2(s[2 * kk][0],     s[2 * kk][1]);
            pa[1] = pack_h2(s[2 * kk][2],     s[2 * kk][3]);
            pa[2] = pack_h2(s[2 * kk + 1][0], s[2 * kk + 1][1]);
            pa[3] = pack_h2(s[2 * kk + 1][2], s[2 * kk + 1][3]);
#pragma unroll
            for (int p = 0; p < 4; p++) {
                unsigned vb[4];
                unsigned off = (unsigned)((kk * 16 + v_kr) * ASTR + p * 16 + v_col) * 2;
                ldsm_x4t(vb, sVH + off);
                mma16816h(oacc[2 * p],     pa, &vb[0]);
                mma16816h(oacc[2 * p + 1], pa, &vb[2]);
            }
        }
        __syncthreads();
    }

    float i0 = 1.0f / (65536.0f * l0);
    float i1 = 1.0f / (65536.0f * l1);
    int r0  = tok0 + q0 + wm + (lane >> 2);
    int col = h * DHEAD + ((lane & 3) << 1);
#pragma unroll
    for (int nb = 0; nb < 8; nb++) {
        size_t p0 = (size_t)r0 * CDIM + col + nb * 8;
        size_t p1 = (size_t)(r0 + 8) * CDIM + col + nb * 8;
        *(unsigned*)(oh + p0) = pack_h2(oacc[nb][0] * i0, oacc[nb][1] * i0);
        *(unsigned*)(oh + p1) = pack_h2(oacc[nb][2] * i1, oacc[nb][3] * i1);
    }
}

// ------------- fused tail: final LN + out-head GEMV + postprocess ----------
__global__ void __launch_bounds__(64)
tail_kernel(const float* __restrict__ hbuf,
            const float* __restrict__ w,
            const float* __restrict__ bo,
            const int*   __restrict__ coords,
            const float* __restrict__ perturb,
            float* __restrict__ out)
{
    __shared__ float row[CDIM];
    __shared__ float ws[4];
    __shared__ float res[OUTC];

    int n = blockIdx.x;
    int tid = threadIdx.x;
    int warp = tid >> 5, lane = tid & 31;

    const float4* xr = (const float4*)(hbuf + (size_t)n * CDIM);
    float4 v0 = xr[tid];
    float4 v1 = xr[tid + 64];
    float s  = v0.x + v0.y + v0.z + v0.w + v1.x + v1.y + v1.z + v1.w;
    float s2 = v0.x * v0.x + v0.y * v0.y + v0.z * v0.z + v0.w * v0.w
             + v1.x * v1.x + v1.y * v1.y + v1.z * v1.z + v1.w * v1.w;
#pragma unroll
    for (int off = 16; off; off >>= 1) {
        s  += __shfl_xor_sync(0xffffffffu, s,  off);
        s2 += __shfl_xor_sync(0xffffffffu, s2, off);
    }
    if (lane == 0) { ws[warp] = s; ws[warp + 2] = s2; }
    __syncthreads();
    float ts  = ws[0] + ws[1];
    float ts2 = ws[2] + ws[3];
    float mean = ts * (1.0f / 512.0f);
    float var  = ts2 * (1.0f / 512.0f) - mean * mean;
    if (var < 0.f) var = 0.f;
    float r = rsqrtf(var + 1e-5f);

    *(float4*)(row + tid * 4) =
        make_float4((v0.x - mean) * r, (v0.y - mean) * r,
                    (v0.z - mean) * r, (v0.w - mean) * r);
    *(float4*)(row + 256 + tid * 4) =
        make_float4((v1.x - mean) * r, (v1.y - mean) * r,
                    (v1.z - mean) * r, (v1.w - mean) * r);
    __syncthreads();

    if (tid < OUTC) {
        float acc = bo[tid];
#pragma unroll 8
        for (int k = 0; k < CDIM; k++)
            acc += row[k] * w[k * OUTC + tid];
        res[tid] = acc;
    }
    __syncthreads();

    if (tid < NGAUSS) {
        int g = tid;
        int idx = n * NGAUSS + g;
#pragma unroll
        for (int j = 0; j < 3; j++) {
            float off = tanhf(res[g * 3 + j] + perturb[g * 3 + j]) * 4.8828125e-4f;
            float xb  = ((float)coords[n * 4 + 1 + j] + 0.5f) * 0.0625f;
            out[idx * 3 + j]          = xb + off;
            out[49152 + idx * 3 + j]  = res[12 + g * 3 + j];
            out[98304 + idx * 3 + j]  = res[24 + g * 3 + j];
        }
#pragma unroll
        for (int j = 0; j < 4; j++)
            out[147456 + idx * 4 + j] = res[36 + g * 4 + j];
        out[212992 + idx] = res[52 + g];
    }
}

// ------------------------------- launch ------------------------------------
extern "C" void kernel_launch(void* const* d_in, const int* in_sizes, int n_in,
                              void* d_out, int out_size)
{
    const float* feats   = (const float*)d_in[0];
    const int*   coords  = (const int*)  d_in[1];
    const float* emb_x   = (const float*)d_in[2];
    const float* emb_y   = (const float*)d_in[3];
    const float* emb_z   = (const float*)d_in[4];
    const float* w_in    = (const float*)d_in[5];
    const float* b_in    = (const float*)d_in[6];
    const float* ln1_g   = (const float*)d_in[7];
    const float* ln1_b   = (const float*)d_in[8];
    const float* w_qkv   = (const float*)d_in[9];
    const float* b_qkv   = (const float*)d_in[10];
    const float* w_o     = (const float*)d_in[11];
    const float* b_o     = (const float*)d_in[12];
    const float* ln2_g   = (const float*)d_in[13];
    const float* ln2_b   = (const float*)d_in[14];
    const float* w_m1    = (const float*)d_in[15];
    const float* b_m1    = (const float*)d_in[16];
    const float* w_m2    = (const float*)d_in[17];
    const float* b_m2    = (const float*)d_in[18];
    const float* w_out   = (const float*)d_in[19];
    const float* b_out   = (const float*)d_in[20];
    const float* perturb = (const float*)d_in[21];
    float* out = (float*)d_out;

    float *ph;
    __half *pah, *pqh, *poh, *pmh;
    __half *pwqh, *pwoh, *pw1h, *pw2h;
    cudaGetSymbolAddress((void**)&ph,   g_h);
    cudaGetSymbolAddress((void**)&pah,  g_ah);
    cudaGetSymbolAddress((void**)&pqh,  g_qh);
    cudaGetSymbolAddress((void**)&poh,  g_oh);
    cudaGetSymbolAddress((void**)&pmh,  g_mh);
    cudaGetSymbolAddress((void**)&pwqh, g_wqkv_h);
    cudaGetSymbolAddress((void**)&pwoh, g_wo_h);
    cudaGetSymbolAddress((void**)&pw1h, g_wm1_h);
    cudaGetSymbolAddress((void**)&pw2h, g_wm2_h);

    cudaFuncSetAttribute(attn_mma_kernel,
                         cudaFuncAttributeMaxDynamicSharedMemorySize, ATT_SMEM);
    cudaFuncSetAttribute(gemm_f16_kernel<4>,
                         cudaFuncAttributeMaxDynamicSharedMemorySize, GSMEM_128);
    cudaFuncSetAttribute(gemm_f16_kernel<2>,
                         cudaFuncAttributeMaxDynamicSharedMemorySize, GSMEM_64);

    {
        int n4q = LAYERS * CDIM * 3 * CDIM / 4;
        int n4o = LAYERS * CDIM * CDIM / 4;
        int n4m = LAYERS * CDIM * MLPDIM / 4;
        int tot = n4q + n4o + 2 * n4m;
        wcast_all_kernel<<<(tot + 255) / 256, 256>>>(
            w_qkv, pwqh, n4q, w_o, pwoh, n4o,
            w_m1, pw1h, n4m, w_m2, pw2h, n4m);
    }

    embed_kernel<<<NTOK, CDIM>>>(feats, coords, emb_x, emb_y, emb_z, w_in, b_in);

    for (int l = 0; l < LAYERS; l++) {
        ln_kernel<<<NTOK / 8, 256>>>(ph, ln1_g + l * CDIM, ln1_b + l * CDIM,
                                     pah, 1e-6f);
        gemm_f16_kernel<4><<<dim3(3 * CDIM / BN, NTOK / 128), 256, GSMEM_128>>>(
            pah, pwqh + (size_t)l * CDIM * 3 * CDIM,
            b_qkv + l * 3 * CDIM, nullptr, pqh,
            NTOK, 3 * CDIM, CDIM, 3);
        attn_mma_kernel<<<dim3(8, HEADS, 8), 128, ATT_SMEM>>>(pqh, poh);
        gemm_f16_kernel<2><<<dim3(CDIM / BN, NTOK / 64), 256, GSMEM_64>>>(
            poh, pwoh + (size_t)l * CDIM * CDIM,
            b_o + l * CDIM, ph, nullptr,
            NTOK, CDIM, CDIM, 1);
        ln_kernel<<<NTOK / 8, 256>>>(ph, ln2_g + l * CDIM, ln2_b + l * CDIM,
                                     pah, 1e-6f);
        gemm_f16_kernel<4><<<dim3(MLPDIM / BN, NTOK / 128), 256, GSMEM_128>>>(
            pah, pw1h + (size_t)l * CDIM * MLPDIM,
            b_m1 + l * MLPDIM, nullptr, pmh,
            NTOK, MLPDIM, CDIM, 2);
        gemm_f16_kernel<2><<<dim3(CDIM / BN, NTOK / 64), 256, GSMEM_64>>>(
            pmh, pw2h + (size_t)l * MLPDIM * CDIM,
            b_m2 + l * CDIM, ph, nullptr,
            NTOK, CDIM, MLPDIM, 1);
    }

    tail_kernel<<<NTOK, 64>>>(ph, w_out, b_out, coords, perturb, out);
}